// round 7
// baseline (speedup 1.0000x reference)
#include <cuda_runtime.h>
#include <cooperative_groups.h>
#include <cstdint>

namespace cg = cooperative_groups;

#define B_ROWS      8192
#define FEATURE_NUM 200
#define NUMERIC_SZ  100
#define IN_W        (FEATURE_NUM + NUMERIC_SZ)   // 300
#define EMBED       64
#define NBLOCKS     256
#define NTHREADS    512                            // 16 warps
#define ROWS_PB     32                             // 2 rows per warp
#define NBINS       64                             // bin = id >> 14 (4MB regions)
#define NPHASES     6

// phase p covers bins [PH_LO[p], PH_HI[p]) ; phase 0 = hot 64MB (pinned)
__device__ __constant__ const int PH_LO[NPHASES] = {0, 16, 26, 35, 44, 53};
__device__ __constant__ const int PH_HI[NPHASES] = {16, 26, 35, 44, 53, 62};

__device__ __forceinline__ float2 ldg2_pol(const float2* p, unsigned long long pol)
{
    float2 v;
    asm volatile("ld.global.nc.L2::cache_hint.v2.f32 {%0,%1}, [%2], %3;"
                 : "=f"(v.x), "=f"(v.y) : "l"(p), "l"(pol));
    return v;
}
__device__ __forceinline__ float ldg_pol(const float* p, unsigned long long pol)
{
    float v;
    asm volatile("ld.global.nc.L2::cache_hint.f32 %0, [%1], %2;"
                 : "=f"(v) : "l"(p), "l"(pol));
    return v;
}

// per-warp 64-bin bucket sort of one row's 200 ids; bin[] ends as END offsets
__device__ __forceinline__ void sort_row(const float* in_row, int* sorted,
                                         int* bin, int lane)
{
    bin[lane] = 0;  bin[lane + 32] = 0;
    __syncwarp();
    int my[7];
    #pragma unroll
    for (int k = 0; k < 7; k++) {
        int j = lane + k * 32;
        my[k] = (j < FEATURE_NUM) ? (int)in_row[j] : -1;
        if (my[k] >= 0) atomicAdd(&bin[my[k] >> 14], 1);
    }
    __syncwarp();
    int c0 = bin[lane], c1 = bin[lane + 32];
    int i0 = c0, i1 = c1;
    #pragma unroll
    for (int off = 1; off < 32; off <<= 1) {
        int t0 = __shfl_up_sync(0xffffffffu, i0, off);
        int t1 = __shfl_up_sync(0xffffffffu, i1, off);
        if (lane >= off) { i0 += t0; i1 += t1; }
    }
    int tot0 = __shfl_sync(0xffffffffu, i0, 31);
    i1 += tot0;
    __syncwarp();
    bin[lane]      = i0 - c0;      // exclusive starts
    bin[lane + 32] = i1 - c1;
    __syncwarp();
    #pragma unroll
    for (int k = 0; k < 7; k++)
        if (my[k] >= 0) {
            int pos = atomicAdd(&bin[my[k] >> 14], 1);
            sorted[pos] = my[k];
        }
    __syncwarp();                  // bin[b] now == end(b)
}

template<bool HOT>
__device__ __forceinline__ void gather_range(const float2* vtab,
                                             const float*  w1,
                                             const int* sorted,
                                             int p0, int p1, int lane,
                                             unsigned long long pol,
                                             float2& s, float2& ss, float& fo)
{
    #pragma unroll 4
    for (int p = p0; p < p1; p++) {
        int id = sorted[p];
        float2 v = HOT ? ldg2_pol(&vtab[(long)id * 32 + lane], pol)
                       : __ldg  (&vtab[(long)id * 32 + lane]);
        s.x += v.x;  s.y += v.y;
        ss.x = fmaf(v.x, v.x, ss.x);
        ss.y = fmaf(v.y, v.y, ss.y);
        if (lane == 0)
            fo += HOT ? ldg_pol(&w1[id], pol) : __ldg(&w1[id]);
    }
}

__global__ __launch_bounds__(NTHREADS, 2)
void fm_kernel(const float* __restrict__ inputs,
               const float* __restrict__ w_one_hot,
               const float* __restrict__ w_numeric,
               const float* __restrict__ v_one_hot,
               const float* __restrict__ v_numeric,
               const float* __restrict__ bias,
               float* __restrict__ out)
{
    __shared__ int s_sorted[ROWS_PB][FEATURE_NUM];   // 25.6 KB
    __shared__ int s_bin[ROWS_PB][NBINS];            //  8   KB

    cg::grid_group grid = cg::this_grid();

    unsigned long long pol_last;
    asm("createpolicy.fractional.L2::evict_last.b64 %0, 1.0;" : "=l"(pol_last));

    const int tid  = threadIdx.x;
    const int lane = tid & 31;
    const int w    = tid >> 5;
    const int rA   = 2 * w, rB = 2 * w + 1;
    const int gA   = blockIdx.x * ROWS_PB + rA;
    const int gB   = gA + 1;
    const float* inA = inputs + (long)gA * IN_W;
    const float* inB = inputs + (long)gB * IN_W;

    sort_row(inA, s_sorted[rA], s_bin[rA], lane);
    sort_row(inB, s_sorted[rB], s_bin[rB], lane);

    const float2* vtab = (const float2*)v_one_hot;
    const float2* vnum = (const float2*)v_numeric;

    float2 sA  = make_float2(0.f, 0.f), ssA = make_float2(0.f, 0.f);
    float2 sB  = make_float2(0.f, 0.f), ssB = make_float2(0.f, 0.f);
    float  foA = 0.f, foB = 0.f;

    // ---- dense numeric part (L1/L2-resident tables) ----
    #pragma unroll 4
    for (int k = 0; k < NUMERIC_SZ; k++) {
        float  nA = __ldg(&inA[FEATURE_NUM + k]);
        float  nB = __ldg(&inB[FEATURE_NUM + k]);
        float2 v  = __ldg(&vnum[k * 32 + lane]);
        float ax = nA * v.x, ay = nA * v.y, bx = nB * v.x, by = nB * v.y;
        sA.x += ax;  sA.y += ay;   sB.x += bx;  sB.y += by;
        ssA.x = fmaf(ax, ax, ssA.x);  ssA.y = fmaf(ay, ay, ssA.y);
        ssB.x = fmaf(bx, bx, ssB.x);  ssB.y = fmaf(by, by, ssB.y);
        if (lane == 0) {
            float wk = __ldg(&w_numeric[k]);
            foA = fmaf(nA, wk, foA);
            foB = fmaf(nB, wk, foB);
        }
    }

    // ---- phased sparse gather: grid-synchronized table sweep ----
    #pragma unroll 1
    for (int ph = 0; ph < NPHASES; ph++) {
        if (ph > 0) grid.sync();               // keep every block in-phase
        int lo = PH_LO[ph], hi = PH_HI[ph];
        int p0A = lo ? s_bin[rA][lo - 1] : 0,  p1A = s_bin[rA][hi - 1];
        int p0B = lo ? s_bin[rB][lo - 1] : 0,  p1B = s_bin[rB][hi - 1];
        if (ph == 0) {
            gather_range<true >(vtab, w_one_hot, s_sorted[rA], p0A, p1A, lane, pol_last, sA, ssA, foA);
            gather_range<true >(vtab, w_one_hot, s_sorted[rB], p0B, p1B, lane, pol_last, sB, ssB, foB);
        } else {
            gather_range<false>(vtab, w_one_hot, s_sorted[rA], p0A, p1A, lane, pol_last, sA, ssA, foA);
            gather_range<false>(vtab, w_one_hot, s_sorted[rB], p0B, p1B, lane, pol_last, sB, ssB, foB);
        }
    }

    // ---- combine + warp reduce (fo lives only in lane 0) ----
    float valA = fmaf(0.5f, fmaf(sA.x, sA.x, -ssA.x) + fmaf(sA.y, sA.y, -ssA.y), foA);
    float valB = fmaf(0.5f, fmaf(sB.x, sB.x, -ssB.x) + fmaf(sB.y, sB.y, -ssB.y), foB);
    #pragma unroll
    for (int off = 16; off > 0; off >>= 1) {
        valA += __shfl_xor_sync(0xffffffffu, valA, off);
        valB += __shfl_xor_sync(0xffffffffu, valB, off);
    }
    if (lane == 0) {
        float b0 = bias[0];
        out[gA] = valA + b0;
        out[gB] = valB + b0;
    }
}

extern "C" void kernel_launch(void* const* d_in, const int* in_sizes, int n_in,
                              void* d_out, int out_size)
{
    const float* inputs    = (const float*)d_in[0];
    const float* w_one_hot = (const float*)d_in[1];
    const float* w_numeric = (const float*)d_in[2];
    const float* v_one_hot = (const float*)d_in[3];
    const float* v_numeric = (const float*)d_in[4];
    const float* bias      = (const float*)d_in[5];
    float* out = (float*)d_out;

    cudaFuncSetAttribute(fm_kernel,
                         cudaFuncAttributePreferredSharedMemoryCarveout, 100);

    void* args[7] = { (void*)&inputs, (void*)&w_one_hot, (void*)&w_numeric,
                      (void*)&v_one_hot, (void*)&v_numeric, (void*)&bias,
                      (void*)&out };
    cudaLaunchCooperativeKernel((void*)fm_kernel,
                                dim3(NBLOCKS), dim3(NTHREADS),
                                args, 0, (cudaStream_t)0);
}

// round 8
// speedup vs baseline: 1.1315x; 1.1315x over previous
#include <cuda_runtime.h>
#include <cooperative_groups.h>
#include <cstdint>

namespace cg = cooperative_groups;

#define B_ROWS      8192
#define FEATURE_NUM 200
#define NUMERIC_SZ  100
#define IN_W        (FEATURE_NUM + NUMERIC_SZ)   // 300
#define EMBED       64
#define NTHREADS    256
#define WARPS       8
#define ROWS_PB     16                            // 2 rows per warp
#define NBLOCKS     (B_ROWS / ROWS_PB)            // 512 (co-resident @4/SM)
#define NBINS       64                            // bin = id >> 14 (4MB)
#define CH          4                             // ids per pipeline stage
#define STAGE_B     (CH * EMBED * 4)              // 1024 B
#define NPHASES     6

__device__ __forceinline__ float ldg_pol(const float* p, unsigned long long pol)
{
    float v;
    asm volatile("ld.global.nc.L2::cache_hint.f32 %0, [%1], %2;"
                 : "=f"(v) : "l"(p), "l"(pol));
    return v;
}

// per-warp 64-bin bucket sort of one row's 200 ids; bin[] left as END offsets
__device__ __forceinline__ void sort_row(const float* in_row, int* sorted,
                                         int* bin, int lane)
{
    bin[lane] = 0;  bin[lane + 32] = 0;
    __syncwarp();
    int my[7];
    #pragma unroll
    for (int k = 0; k < 7; k++) {
        int j = lane + k * 32;
        my[k] = (j < FEATURE_NUM) ? (int)in_row[j] : -1;
        if (my[k] >= 0) atomicAdd(&bin[my[k] >> 14], 1);
    }
    __syncwarp();
    int c0 = bin[lane], c1 = bin[lane + 32];
    int i0 = c0, i1 = c1;
    #pragma unroll
    for (int off = 1; off < 32; off <<= 1) {
        int t0 = __shfl_up_sync(0xffffffffu, i0, off);
        int t1 = __shfl_up_sync(0xffffffffu, i1, off);
        if (lane >= off) { i0 += t0; i1 += t1; }
    }
    int tot0 = __shfl_sync(0xffffffffu, i0, 31);
    i1 += tot0;
    __syncwarp();
    bin[lane]      = i0 - c0;
    bin[lane + 32] = i1 - c1;
    __syncwarp();
    #pragma unroll
    for (int k = 0; k < 7; k++)
        if (my[k] >= 0) {
            int pos = atomicAdd(&bin[my[k] >> 14], 1);
            sorted[pos] = my[k];
        }
    __syncwarp();                  // bin[b] == end(b)
}

__global__ __launch_bounds__(NTHREADS, 4)
void fm_kernel(const float* __restrict__ inputs,
               const float* __restrict__ w_one_hot,
               const float* __restrict__ w_numeric,
               const float* __restrict__ v_one_hot,
               const float* __restrict__ v_numeric,
               const float* __restrict__ bias,
               float* __restrict__ out)
{
    __shared__ int s_sorted[ROWS_PB][FEATURE_NUM];            // 12.8 KB
    __shared__ int s_end[ROWS_PB][NBINS];                     //  4   KB
    __shared__ __align__(16) char s_buf[WARPS][2][STAGE_B];   // 16   KB

    cg::grid_group grid = cg::this_grid();

    unsigned long long pol_last;
    asm("createpolicy.fractional.L2::evict_last.b64 %0, 1.0;" : "=l"(pol_last));

    const int tid  = threadIdx.x;
    const int lane = tid & 31;
    const int w    = tid >> 5;
    const int rA   = 2 * w, rB = rA + 1;
    const int gA   = blockIdx.x * ROWS_PB + rA;
    const float* inA = inputs + (long)gA * IN_W;
    const float* inB = inA + IN_W;

    sort_row(inA, s_sorted[rA], s_end[rA], lane);
    sort_row(inB, s_sorted[rB], s_end[rB], lane);

    float2 sA  = make_float2(0.f, 0.f), ssA = make_float2(0.f, 0.f);
    float2 sB  = make_float2(0.f, 0.f), ssB = make_float2(0.f, 0.f);
    float  foA = 0.f, foB = 0.f;

    // ---- dense numeric part (tables cache-resident) ----
    {
        const float2* vnum = (const float2*)v_numeric;
        #pragma unroll 4
        for (int k = 0; k < NUMERIC_SZ; k++) {
            float  nA = __ldg(&inA[FEATURE_NUM + k]);
            float  nB = __ldg(&inB[FEATURE_NUM + k]);
            float2 v  = __ldg(&vnum[k * 32 + lane]);
            float ax = nA * v.x, ay = nA * v.y, bx = nB * v.x, by = nB * v.y;
            sA.x += ax;  sA.y += ay;   sB.x += bx;  sB.y += by;
            ssA.x = fmaf(ax, ax, ssA.x);  ssA.y = fmaf(ay, ay, ssA.y);
            ssB.x = fmaf(bx, bx, ssB.x);  ssB.y = fmaf(by, by, ssB.y);
        }
        #pragma unroll
        for (int k = lane; k < NUMERIC_SZ; k += 32) {
            float wk = __ldg(&w_numeric[k]);
            foA = fmaf(__ldg(&inA[FEATURE_NUM + k]), wk, foA);
            foB = fmaf(__ldg(&inB[FEATURE_NUM + k]), wk, foB);
        }
    }

    // ---- phased, grid-synchronized, cp.async-pipelined sparse gather ----
    const int ph_lo[NPHASES + 1] = {0, 16, 26, 35, 44, 53, 64};
    const unsigned int buf0 =
        (unsigned int)__cvta_generic_to_shared(&s_buf[w][0][0]);

    #pragma unroll 1
    for (int ph = 0; ph < NPHASES; ph++) {
        if (ph > 0) grid.sync();                 // all blocks sweep in-phase
        const int lo = ph_lo[ph], hi = ph_lo[ph + 1];
        const int p0A = lo ? s_end[rA][lo - 1] : 0, p1A = s_end[rA][hi - 1];
        const int p0B = lo ? s_end[rB][lo - 1] : 0, p1B = s_end[rB][hi - 1];
        const int lenA = p1A - p0A;
        const int T    = lenA + (p1B - p0B);
        if (T <= 0) continue;
        const int* pA = &s_sorted[rA][p0A];
        const int* pB = &s_sorted[rB][p0B];
        const bool hot = (ph == 0);
        const int  nst = (T + CH - 1) / CH;

        auto issue = [&](int st, int slot) {
            unsigned int dst = buf0 + slot * STAGE_B;
            #pragma unroll
            for (int t = 0; t < 2; t++) {
                int c = lane + t * 32;               // 0..63 : 16B chunk
                int k = st * CH + (c >> 4);
                if (k >= T) k = T - 1;               // clamp (redundant load)
                int id = (k < lenA) ? pA[k] : pB[k - lenA];
                const char* src = (const char*)(v_one_hot + (long)id * EMBED)
                                + (c & 15) * 16;
                if (hot)
                    asm volatile(
                        "cp.async.cg.shared.global.L2::cache_hint [%0], [%1], 16, %2;"
                        :: "r"(dst + c * 16), "l"(src), "l"(pol_last) : "memory");
                else
                    asm volatile(
                        "cp.async.cg.shared.global [%0], [%1], 16;"
                        :: "r"(dst + c * 16), "l"(src) : "memory");
            }
            asm volatile("cp.async.commit_group;" ::: "memory");
        };

        issue(0, 0);
        if (nst > 1) issue(1, 1); else asm volatile("cp.async.commit_group;" ::: "memory");

        #pragma unroll 1
        for (int st = 0; st < nst; st++) {
            if (st + 2 < nst)
                asm volatile("cp.async.wait_group 1;" ::: "memory");
            else
                asm volatile("cp.async.wait_group 0;" ::: "memory");
            __syncwarp();
            const float2* bp = (const float2*)&s_buf[w][st & 1][0];
            #pragma unroll
            for (int i = 0; i < CH; i++) {
                int k = st * CH + i;
                if (k < T) {
                    float2 v = bp[i * 32 + lane];
                    if (k < lenA) {
                        sA.x += v.x;  sA.y += v.y;
                        ssA.x = fmaf(v.x, v.x, ssA.x);
                        ssA.y = fmaf(v.y, v.y, ssA.y);
                    } else {
                        sB.x += v.x;  sB.y += v.y;
                        ssB.x = fmaf(v.x, v.x, ssB.x);
                        ssB.y = fmaf(v.y, v.y, ssB.y);
                    }
                }
            }
            __syncwarp();
            if (st + 2 < nst) issue(st + 2, st & 1);
        }
    }

    // ---- first-order sparse part (4MB pinned table, lane-parallel) ----
    #pragma unroll
    for (int k = 0; k < 7; k++) {
        int j = lane + k * 32;
        if (j < FEATURE_NUM) {
            foA += ldg_pol(&w_one_hot[s_sorted[rA][j]], pol_last);
            foB += ldg_pol(&w_one_hot[s_sorted[rB][j]], pol_last);
        }
    }

    // ---- combine + warp reduce ----
    float valA = fmaf(0.5f, fmaf(sA.x, sA.x, -ssA.x) + fmaf(sA.y, sA.y, -ssA.y), foA);
    float valB = fmaf(0.5f, fmaf(sB.x, sB.x, -ssB.x) + fmaf(sB.y, sB.y, -ssB.y), foB);
    #pragma unroll
    for (int off = 16; off > 0; off >>= 1) {
        valA += __shfl_xor_sync(0xffffffffu, valA, off);
        valB += __shfl_xor_sync(0xffffffffu, valB, off);
    }
    if (lane == 0) {
        float b0 = bias[0];
        out[gA]     = valA + b0;
        out[gA + 1] = valB + b0;
    }
}

extern "C" void kernel_launch(void* const* d_in, const int* in_sizes, int n_in,
                              void* d_out, int out_size)
{
    const float* inputs    = (const float*)d_in[0];
    const float* w_one_hot = (const float*)d_in[1];
    const float* w_numeric = (const float*)d_in[2];
    const float* v_one_hot = (const float*)d_in[3];
    const float* v_numeric = (const float*)d_in[4];
    const float* bias      = (const float*)d_in[5];
    float* out = (float*)d_out;

    void* args[7] = { (void*)&inputs, (void*)&w_one_hot, (void*)&w_numeric,
                      (void*)&v_one_hot, (void*)&v_numeric, (void*)&bias,
                      (void*)&out };
    cudaLaunchCooperativeKernel((void*)fm_kernel,
                                dim3(NBLOCKS), dim3(NTHREADS),
                                args, 0, (cudaStream_t)0);
}

// round 9
// speedup vs baseline: 1.2237x; 1.0816x over previous
#include <cuda_runtime.h>
#include <cstdint>

#define B_ROWS      8192
#define FEATURE_NUM 200
#define NUMERIC_SZ  100
#define IN_W        (FEATURE_NUM + NUMERIC_SZ)   // 300
#define EMBED       64
#define NTHREADS    256
#define WARPS       8                             // one row per warp
#define NBLOCKS     (B_ROWS / WARPS)              // 1024
#define NBINS       64                            // bin = id >> 14 (4MB regions)
#define NPHASES     6

// phase boundaries in bins; phase 0 = bins [0,18) = 72MB hot (pinned)
__constant__ int c_phb[NPHASES + 1] = {0, 18, 27, 36, 45, 53, 64};

// persistent scratch (__device__ globals: allowed; no allocation)
__device__ int    g_sorted[B_ROWS * FEATURE_NUM];     // 6.55 MB
__device__ int    g_off[B_ROWS][NPHASES + 1];         // offsets into sorted list
__device__ float2 g_S[B_ROWS * 32];                   // per-dim sums (2 dims/lane)
__device__ float  g_ss[B_ROWS];                       // sum of squares (scalar)
__device__ float  g_fo[B_ROWS];                       // first-order sparse part

__device__ __forceinline__ float2 ldg2_pol(const float2* p, unsigned long long pol)
{
    float2 v;
    asm volatile("ld.global.nc.L2::cache_hint.v2.f32 {%0,%1}, [%2], %3;"
                 : "=f"(v.x), "=f"(v.y) : "l"(p), "l"(pol));
    return v;
}
__device__ __forceinline__ float ldg_pol(const float* p, unsigned long long pol)
{
    float v;
    asm volatile("ld.global.nc.L2::cache_hint.f32 %0, [%1], %2;"
                 : "=f"(v) : "l"(p), "l"(pol));
    return v;
}
__device__ __forceinline__ unsigned long long mk_pol_last()
{
    unsigned long long p;
    asm("createpolicy.fractional.L2::evict_last.b64 %0, 1.0;" : "=l"(p));
    return p;
}

// ───────────────────────── Kernel A: sort + first-order ─────────────────────
__global__ __launch_bounds__(NTHREADS)
void sort_kernel(const float* __restrict__ inputs,
                 const float* __restrict__ w_one_hot)
{
    __shared__ int s_bin[WARPS][NBINS];

    const unsigned long long pol_last = mk_pol_last();
    const int lane = threadIdx.x & 31;
    const int w    = threadIdx.x >> 5;
    const int row  = blockIdx.x * WARPS + w;
    const float* in_row = inputs + (long)row * IN_W;
    int* bin = s_bin[w];
    int* srt = g_sorted + (long)row * FEATURE_NUM;

    bin[lane] = 0;  bin[lane + 32] = 0;
    __syncwarp();

    int my[7];  float fo = 0.f;
    #pragma unroll
    for (int k = 0; k < 7; k++) {
        int j = lane + k * 32;
        my[k] = (j < FEATURE_NUM) ? (int)in_row[j] : -1;
        if (my[k] >= 0) {
            atomicAdd(&bin[my[k] >> 14], 1);
            fo += ldg_pol(&w_one_hot[my[k]], pol_last);   // 4MB table, pinned
        }
    }
    __syncwarp();

    // warp-parallel exclusive prefix over 64 bins
    int c0 = bin[lane], c1 = bin[lane + 32];
    int i0 = c0, i1 = c1;
    #pragma unroll
    for (int off = 1; off < 32; off <<= 1) {
        int t0 = __shfl_up_sync(0xffffffffu, i0, off);
        int t1 = __shfl_up_sync(0xffffffffu, i1, off);
        if (lane >= off) { i0 += t0; i1 += t1; }
    }
    int tot0 = __shfl_sync(0xffffffffu, i0, 31);
    i1 += tot0;
    __syncwarp();
    bin[lane]      = i0 - c0;          // exclusive starts
    bin[lane + 32] = i1 - c1;
    __syncwarp();

    // phase offsets from exclusive starts (before scatter mutates bins)
    if (lane <= NPHASES) {
        int b = c_phb[lane];
        g_off[row][lane] = (b >= NBINS) ? FEATURE_NUM : bin[b];
    }
    __syncwarp();

    #pragma unroll
    for (int k = 0; k < 7; k++)
        if (my[k] >= 0) {
            int pos = atomicAdd(&bin[my[k] >> 14], 1);
            srt[pos] = my[k];
        }

    // reduce first-order into g_fo
    #pragma unroll
    for (int off = 16; off > 0; off >>= 1)
        fo += __shfl_xor_sync(0xffffffffu, fo, off);
    if (lane == 0) g_fo[row] = fo;
}

// ───────────────────────── Phase kernel: windowed gather ────────────────────
__global__ __launch_bounds__(NTHREADS)
void phase_kernel(const float* __restrict__ v_one_hot, int ph)
{
    const int lane = threadIdx.x & 31;
    const int w    = threadIdx.x >> 5;
    const int row  = blockIdx.x * WARPS + w;

    const int p0 = g_off[row][ph];
    const int p1 = g_off[row][ph + 1];
    const int* srt = g_sorted + (long)row * FEATURE_NUM;
    const float2* vtab = (const float2*)v_one_hot;

    float2 s  = make_float2(0.f, 0.f);
    float  ss = 0.f;

    if (ph == 0) {
        const unsigned long long pol_last = mk_pol_last();
        #pragma unroll 4
        for (int j = p0; j < p1; j++) {
            int id = __ldg(&srt[j]);
            float2 v = ldg2_pol(&vtab[(long)id * 32 + lane], pol_last);
            s.x += v.x;  s.y += v.y;
            ss = fmaf(v.x, v.x, fmaf(v.y, v.y, ss));
        }
    } else {
        #pragma unroll 4
        for (int j = p0; j < p1; j++) {
            int id = __ldg(&srt[j]);
            float2 v = __ldg(&vtab[(long)id * 32 + lane]);  // default policy:
            s.x += v.x;  s.y += v.y;                        // window cached in L2
            ss = fmaf(v.x, v.x, fmaf(v.y, v.y, ss));
        }
    }

    // scalar ss: warp reduce
    #pragma unroll
    for (int off = 16; off > 0; off >>= 1)
        ss += __shfl_xor_sync(0xffffffffu, ss, off);

    // exclusive row ownership + stream-serialized phases -> plain RMW
    if (ph == 0) {
        g_S[row * 32 + lane] = s;
        if (lane == 0) g_ss[row] = ss;
    } else {
        float2 acc = g_S[row * 32 + lane];
        acc.x += s.x;  acc.y += s.y;
        g_S[row * 32 + lane] = acc;
        if (lane == 0) g_ss[row] += ss;
    }
}

// ───────────────────────── Kernel F: numeric + combine ──────────────────────
__global__ __launch_bounds__(NTHREADS)
void final_kernel(const float* __restrict__ inputs,
                  const float* __restrict__ w_numeric,
                  const float* __restrict__ v_numeric,
                  const float* __restrict__ bias,
                  float* __restrict__ out)
{
    const int lane = threadIdx.x & 31;
    const int w    = threadIdx.x >> 5;
    const int row  = blockIdx.x * WARPS + w;
    const float* in_row = inputs + (long)row * IN_W + FEATURE_NUM;
    const float2* vnum  = (const float2*)v_numeric;

    float2 s  = g_S[row * 32 + lane];
    float  ss = 0.f, fo = 0.f;

    #pragma unroll 4
    for (int k = 0; k < NUMERIC_SZ; k++) {
        float  n = __ldg(&in_row[k]);
        float2 v = __ldg(&vnum[k * 32 + lane]);
        float tx = n * v.x, ty = n * v.y;
        s.x += tx;  s.y += ty;
        ss = fmaf(tx, tx, fmaf(ty, ty, ss));
    }
    #pragma unroll
    for (int k = lane; k < NUMERIC_SZ; k += 32)
        fo = fmaf(__ldg(&in_row[k]), __ldg(&w_numeric[k]), fo);

    float val = fmaf(s.x, s.x, fmaf(s.y, s.y, -ss)) * 0.5f + fo;
    #pragma unroll
    for (int off = 16; off > 0; off >>= 1)
        val += __shfl_xor_sync(0xffffffffu, val, off);

    if (lane == 0)
        out[row] = val - 0.5f * g_ss[row] + g_fo[row] + bias[0];
}

extern "C" void kernel_launch(void* const* d_in, const int* in_sizes, int n_in,
                              void* d_out, int out_size)
{
    const float* inputs    = (const float*)d_in[0];
    const float* w_one_hot = (const float*)d_in[1];
    const float* w_numeric = (const float*)d_in[2];
    const float* v_one_hot = (const float*)d_in[3];
    const float* v_numeric = (const float*)d_in[4];
    const float* bias      = (const float*)d_in[5];
    float* out = (float*)d_out;

    sort_kernel<<<NBLOCKS, NTHREADS>>>(inputs, w_one_hot);
    for (int ph = 0; ph < NPHASES; ph++)
        phase_kernel<<<NBLOCKS, NTHREADS>>>(v_one_hot, ph);
    final_kernel<<<NBLOCKS, NTHREADS>>>(inputs, w_numeric, v_numeric, bias, out);
}

// round 10
// speedup vs baseline: 1.8120x; 1.4807x over previous
#include <cuda_runtime.h>
#include <cstdint>

#define B_ROWS      8192
#define FEATURE_NUM 200
#define NUMERIC_SZ  100
#define IN_W        (FEATURE_NUM + NUMERIC_SZ)   // 300
#define EMBED       64
#define ROWS_PB     8                             // one warp per row
#define NTHREADS    (32 * ROWS_PB)                // 256
#define NBINS       64                            // id >> 14
#define HOT_IDS     430000                        // ~110MB pinned in L2
#define CH          4                             // ids per pipeline stage
#define NSTAGES     (FEATURE_NUM / CH)            // 50
#define STAGE_B     (CH * EMBED * 4)              // 1024 bytes

__device__ __forceinline__ float ldg_pol(const float* p, unsigned long long pol)
{
    float v;
    asm volatile("ld.global.nc.L2::cache_hint.f32 %0, [%1], %2;"
                 : "=f"(v) : "l"(p), "l"(pol));
    return v;
}

__global__ __launch_bounds__(NTHREADS)
void fm_kernel(const float* __restrict__ inputs,
               const float* __restrict__ w_one_hot,
               const float* __restrict__ w_numeric,
               const float* __restrict__ v_one_hot,
               const float* __restrict__ v_numeric,
               const float* __restrict__ bias,
               float* __restrict__ out)
{
    __shared__ int   s_sorted[ROWS_PB][FEATURE_NUM];
    __shared__ float s_num[ROWS_PB][NUMERIC_SZ];
    __shared__ int   s_bin[ROWS_PB][NBINS];
    __shared__ __align__(16) char s_buf[ROWS_PB][2][STAGE_B];

    unsigned long long pol_last, pol_first;
    asm("createpolicy.fractional.L2::evict_last.b64 %0, 1.0;"  : "=l"(pol_last));
    asm("createpolicy.fractional.L2::evict_first.b64 %0, 1.0;" : "=l"(pol_first));

    const int tid  = threadIdx.x;
    const int lane = tid & 31;
    const int r    = tid >> 5;
    const int row  = blockIdx.x * ROWS_PB + r;
    const float* in_row = inputs + (long)row * IN_W;

    // ---- per-warp: zero bins, load ids to regs, histogram ----
    s_bin[r][lane] = 0;  s_bin[r][lane + 32] = 0;
    __syncwarp();

    int my_id[7];
    #pragma unroll
    for (int k = 0; k < 7; k++) {
        int j = lane + k * 32;
        my_id[k] = (j < FEATURE_NUM) ? (int)in_row[j] : -1;
        if (my_id[k] >= 0) atomicAdd(&s_bin[r][my_id[k] >> 14], 1);
    }
    // numeric features (warp-local staging)
    #pragma unroll
    for (int k = lane; k < NUMERIC_SZ; k += 32)
        s_num[r][k] = in_row[FEATURE_NUM + k];
    __syncwarp();

    // ---- warp-parallel exclusive prefix over 64 bins ----
    {
        int c0 = s_bin[r][lane], c1 = s_bin[r][lane + 32];
        int i0 = c0, i1 = c1;
        #pragma unroll
        for (int off = 1; off < 32; off <<= 1) {
            int t0 = __shfl_up_sync(0xffffffffu, i0, off);
            int t1 = __shfl_up_sync(0xffffffffu, i1, off);
            if (lane >= off) { i0 += t0; i1 += t1; }
        }
        int tot0 = __shfl_sync(0xffffffffu, i0, 31);
        i1 += tot0;
        s_bin[r][lane]      = i0 - c0;
        s_bin[r][lane + 32] = i1 - c1;
    }
    __syncwarp();

    // ---- scatter into ascending-bin order (approximate sort) ----
    #pragma unroll
    for (int k = 0; k < 7; k++)
        if (my_id[k] >= 0) {
            int pos = atomicAdd(&s_bin[r][my_id[k] >> 14], 1);
            s_sorted[r][pos] = my_id[k];
        }
    __syncwarp();

    // ---- cp.async pipelined gather: register-free MLP ----
    const unsigned int buf0 =
        (unsigned int)__cvta_generic_to_shared(&s_buf[r][0][0]);

    auto issue_stage = [&](int st, int slot) {
        unsigned int dst = buf0 + slot * STAGE_B;
        #pragma unroll
        for (int t = 0; t < 2; t++) {
            int c  = lane + t * 32;                  // 0..63 : 16B chunk
            int id = s_sorted[r][st * CH + (c >> 4)];
            const char* src = (const char*)(v_one_hot + (long)id * EMBED)
                            + (c & 15) * 16;
            unsigned long long pol = (id < HOT_IDS) ? pol_last : pol_first;
            asm volatile("cp.async.cg.shared.global.L2::cache_hint [%0], [%1], 16, %2;"
                         :: "r"(dst + c * 16), "l"(src), "l"(pol) : "memory");
        }
        asm volatile("cp.async.commit_group;" ::: "memory");
    };

    float2 s  = make_float2(0.f, 0.f);
    float2 ss = make_float2(0.f, 0.f);

    issue_stage(0, 0);
    issue_stage(1, 1);

    #pragma unroll 1
    for (int st = 0; st < NSTAGES; st++) {
        if (st + 2 < NSTAGES)
            asm volatile("cp.async.wait_group 1;" ::: "memory");
        else
            asm volatile("cp.async.wait_group 0;" ::: "memory");
        __syncwarp();

        const float2* bp = (const float2*)&s_buf[r][st & 1][0];
        #pragma unroll
        for (int i = 0; i < CH; i++) {
            float2 v = bp[i * 32 + lane];            // columns 2*lane, 2*lane+1
            s.x += v.x;  s.y += v.y;
            ss.x = fmaf(v.x, v.x, ss.x);
            ss.y = fmaf(v.y, v.y, ss.y);
        }
        __syncwarp();
        if (st + 2 < NSTAGES) issue_stage(st + 2, st & 1);
    }

    // ---- first-order sparse part (4MB table: pinned, L2 hits) ----
    float fo = 0.f;
    #pragma unroll
    for (int k = 0; k < 7; k++) {
        int j = lane + k * 32;
        if (j < FEATURE_NUM)
            fo += ldg_pol(&w_one_hot[s_sorted[r][j]], pol_last);
    }

    // ---- dense numeric part ----
    const int c0 = lane * 2;
    #pragma unroll 4
    for (int k = 0; k < NUMERIC_SZ; k++) {
        float  n  = s_num[r][k];
        float2 vn = *(const float2*)&v_numeric[k * EMBED + c0];
        float tx = n * vn.x, ty = n * vn.y;
        s.x += tx;  s.y += ty;
        ss.x = fmaf(tx, tx, ss.x);
        ss.y = fmaf(ty, ty, ss.y);
    }
    #pragma unroll
    for (int k = lane; k < NUMERIC_SZ; k += 32)
        fo = fmaf(s_num[r][k], __ldg(&w_numeric[k]), fo);

    // ---- combine + warp reduce ----
    float so  = fmaf(s.x, s.x, -ss.x) + fmaf(s.y, s.y, -ss.y);
    float val = fmaf(0.5f, so, fo);

    #pragma unroll
    for (int off = 16; off > 0; off >>= 1)
        val += __shfl_xor_sync(0xffffffffu, val, off);

    if (lane == 0)
        out[row] = val + bias[0];
}

extern "C" void kernel_launch(void* const* d_in, const int* in_sizes, int n_in,
                              void* d_out, int out_size)
{
    const float* inputs    = (const float*)d_in[0];
    const float* w_one_hot = (const float*)d_in[1];
    const float* w_numeric = (const float*)d_in[2];
    const float* v_one_hot = (const float*)d_in[3];
    const float* v_numeric = (const float*)d_in[4];
    const float* bias      = (const float*)d_in[5];
    float* out = (float*)d_out;

    fm_kernel<<<B_ROWS / ROWS_PB, NTHREADS>>>(inputs, w_one_hot, w_numeric,
                                              v_one_hot, v_numeric, bias, out);
}